// round 13
// baseline (speedup 1.0000x reference)
#include <cuda_runtime.h>
#include <cuda_bf16.h>
#include <cstdint>

// GDLoss: elementwise Gaussian KL loss over [N,5] xywhr boxes. 176MB traffic.
// R13 = R12 (per-warp autonomous 3-stage cp.async rings, compile-time slots,
// slim math; kernel 28.4us, DRAM 75.0%) re-partitioned into BLK=128 blocks:
// smem/block 15KB -> 15 blocks/SM (60 warps, occ ~92% theoretical) vs R12's
// 7x256 (56 warps, occ 71% measured). More independent CTAs = more eligible
// warps when some sit at cp.async.wait -> higher memory duty cycle.

#define TAU_F   1.0f
#define EPS_F   1e-6f
#define BLK     128
#define NW      (BLK / 32)           // 4 warps
#define STAGES  3
#define WTILE   32                   // boxes per warp-tile
#define WTF     (WTILE * 5)          // 160 floats per tensor per warp-tile
#define GRID_P  2280                 // 15 blocks/SM * 152 SMs

__device__ __forceinline__ void cp_async16(unsigned smem_dst, const void* gmem_src) {
    asm volatile("cp.async.cg.shared.global [%0], [%1], 16;\n"
                 :: "r"(smem_dst), "l"(gmem_src));
}
__device__ __forceinline__ void cp_async4(unsigned smem_dst, const void* gmem_src) {
    asm volatile("cp.async.ca.shared.global [%0], [%1], 4;\n"
                 :: "r"(smem_dst), "l"(gmem_src));
}
__device__ __forceinline__ void cp_commit() {
    asm volatile("cp.async.commit_group;\n" ::: "memory");
}
template <int N>
__device__ __forceinline__ void cp_wait() {
    asm volatile("cp.async.wait_group %0;\n" :: "n"(N) : "memory");
}

__device__ __forceinline__ float rcp_fast(float x) {
    float r; asm("rcp.approx.f32 %0, %1;" : "=f"(r) : "f"(x)); return r;
}
__device__ __forceinline__ float sqrt_fast(float x) {
    float r; asm("sqrt.approx.f32 %0, %1;" : "=f"(r) : "f"(x)); return r;
}

// loss for one box pair (algebraically reduced):
//   det_t = tww*thh/16, det_p = pww*phh/16     (rotation-invariant, no trig)
//   t1num = ths(dx^2+dy^2) - thd(c2t(dx^2-dy^2) + 2 s2t dx dy)
//   n2num = 2(ths*phs - thd*phd*cos(2rt-2rp))
//   dis   = (t1num+n2num)*16/(tww*thh) + log((tww*thh)/(pww*phh)) - 2
__device__ __forceinline__ float gd_loss_one(
    float px, float py, float pw, float ph, float prr,
    float tx, float ty, float tw, float th, float trr)
{
    pw = fminf(fmaxf(pw, 1e-7f), 1e7f);
    ph = fminf(fmaxf(ph, 1e-7f), 1e7f);
    tw = fminf(fmaxf(tw, 1e-7f), 1e7f);
    th = fminf(fmaxf(th, 1e-7f), 1e7f);

    const float pww = pw * pw, phh = ph * ph;
    const float tww = tw * tw, thh = th * th;

    const float phs = 0.125f * (pww + phh);
    const float phd = 0.125f * (pww - phh);
    const float ths = 0.125f * (tww + thh);
    const float thd = 0.125f * (tww - thh);

    float s2t, c2t;
    __sincosf(2.0f * trr, &s2t, &c2t);
    const float cdd = __cosf(2.0f * (trr - prr));   // cos(2rt - 2rp)

    const float dx = px - tx;
    const float dy = py - ty;
    const float dx2 = dx * dx, dy2 = dy * dy;
    const float sum2 = dx2 + dy2, dif2 = dx2 - dy2;
    const float dxy = dx * dy;

    const float rot   = fmaf(c2t, dif2, 2.0f * s2t * dxy);
    const float t1num = fmaf(ths, sum2, -thd * rot);
    const float n2num = 2.0f * fmaf(-thd * phd, cdd, ths * phs);

    const float dtt = tww * thh;                    // 16*det_t
    const float dpp = pww * phh;                    // 16*det_p
    const float invdt16 = 16.0f * rcp_fast(dtt);
    const float logterm = __logf(dtt * rcp_fast(dpp));

    const float dis = fmaf(t1num + n2num, invdt16, logterm - 2.0f);
    const float kl = fmaxf(dis, EPS_F);
    return 1.0f - rcp_fast(TAU_F + sqrt_fast(kl));
}

__global__ void __launch_bounds__(BLK) gd_loss_kernel(
    const float* __restrict__ pred,
    const float* __restrict__ target,
    float* __restrict__ out,
    int n)
{
    // [warp][stage][tensor 0=pred 1=target][160 floats]
    __shared__ float sbuf[NW][STAGES][2][WTF];

    const int lane = threadIdx.x & 31;
    const int wid  = threadIdx.x >> 5;
    const int b5   = lane * 5;

    const int numTiles = (n + WTILE - 1) / WTILE;
    const int wstride  = gridDim.x * NW;
    const int wstart   = blockIdx.x * NW + wid;
    if (wstart >= numTiles) return;

    // Per-warp smem base (shared-space address), one cvta total.
    const unsigned sbase = (unsigned)__cvta_generic_to_shared(&sbuf[wid][0][0][0]);
    const unsigned lane16 = (unsigned)lane * 16u;

    // Issue-side carried state: tile index + gmem pointers, strength-reduced.
    int iTile = wstart;
    const float4* ipp4 = (const float4*)pred   + (size_t)wstart * (WTF / 4);
    const float4* ipt4 = (const float4*)target + (size_t)wstart * (WTF / 4);
    const int ptrStep = wstride * (WTF / 4);     // float4s per issue step

    // ISSUE(SLOT): cp.async this warp's tile `iTile` into compile-time SLOT.
    // Always commits one group; advances carried state.
#define ISSUE(SLOT) do {                                                      \
    if (iTile < numTiles) {                                                   \
        const int inb = n - iTile * WTILE;                                    \
        const unsigned dsp = sbase + (unsigned)((SLOT) * (2 * WTF * 4));      \
        const unsigned dst_ = dsp + (unsigned)(WTF * 4);                      \
        if (inb >= WTILE) {                                                   \
            cp_async16(dsp + lane16, ipp4 + lane);                            \
            cp_async16(dst_ + lane16, ipt4 + lane);                           \
            if (lane < 8) {                                                   \
                cp_async16(dsp + lane16 + 512u, ipp4 + lane + 32);            \
                cp_async16(dst_ + lane16 + 512u, ipt4 + lane + 32);           \
            }                                                                 \
        } else {                                                              \
            const float* pb = (const float*)ipp4;                             \
            const float* tb = (const float*)ipt4;                             \
            const int nf = inb * 5;                                           \
            for (int i = lane; i < nf; i += 32) {                             \
                cp_async4(dsp + (unsigned)i * 4u, pb + i);                    \
                cp_async4(dst_ + (unsigned)i * 4u, tb + i);                   \
            }                                                                 \
        }                                                                     \
    }                                                                         \
    cp_commit();                                                              \
    iTile += wstride; ipp4 += ptrStep; ipt4 += ptrStep;                       \
} while (0)

    // Prologue: two warp-tiles in flight (slots 0, 1).
    ISSUE(0);
    ISSUE(1);

    // Compute-side carried state.
    int tile = wstart;
    float* outp = out + (size_t)wstart * WTILE + lane;
    const int outStep = wstride * WTILE;

    // STEP(SLOT, ISLOT): wait for this tile, refill slot ISLOT, compute+store.
#define STEP(SLOT, ISLOT) do {                                                \
    cp_wait<1>();                                                             \
    __syncwarp();                                                             \
    ISSUE(ISLOT);                                                             \
    {                                                                         \
        const int nb = n - tile * WTILE;                                      \
        const float* spb = sbuf[wid][SLOT][0];                                \
        const float* stb = sbuf[wid][SLOT][1];                                \
        if (lane < nb) {                                                      \
            const float loss = gd_loss_one(                                   \
                spb[b5 + 0], spb[b5 + 1], spb[b5 + 2], spb[b5 + 3], spb[b5 + 4], \
                stb[b5 + 0], stb[b5 + 1], stb[b5 + 2], stb[b5 + 3], stb[b5 + 4]); \
            __stcs(outp, loss);                                               \
        }                                                                     \
    }                                                                         \
    tile += wstride; outp += outStep;                                         \
} while (0)

    for (;;) {
        STEP(0, 2); if (tile >= numTiles) break;
        STEP(1, 0); if (tile >= numTiles) break;
        STEP(2, 1); if (tile >= numTiles) break;
    }

#undef STEP
#undef ISSUE
}

extern "C" void kernel_launch(void* const* d_in, const int* in_sizes, int n_in,
                              void* d_out, int out_size)
{
    const float* pred   = (const float*)d_in[0];
    const float* target = (const float*)d_in[1];
    // d_in[2] (weight) is unused by the reference computation (LOSS_WEIGHT=1).
    float* out = (float*)d_out;

    const int n = out_size;                        // N boxes; output [N,1] floats
    const int numTiles = (n + WTILE - 1) / WTILE;  // 125000 for N=4M
    int grid = GRID_P;
    const int maxGrid = (numTiles + NW - 1) / NW;
    if (grid > maxGrid) grid = maxGrid;
    gd_loss_kernel<<<grid, BLK>>>(pred, target, out, n);
}

// round 14
// speedup vs baseline: 1.0656x; 1.0656x over previous
#include <cuda_runtime.h>
#include <cuda_bf16.h>
#include <cstdint>

// GDLoss: elementwise Gaussian KL loss over [N,5] xywhr boxes. 176MB traffic.
// R14: register double-buffered persistent loop - no smem, no barriers, no
// cp.async bookkeeping. Each thread owns 2 boxes/iteration (10 floats = 5
// aligned float2 per tensor). Next iteration's 10 independent LDG.64 are
// issued before computing the current pair, so load latency for iter k+1 is
// hidden under iter k's ~90 math ops. Fixes R10's exposed-latency failure
// (one-shot loads) while shedding R12's smem round-trip and sync overhead.

#define TAU_F   1.0f
#define EPS_F   1e-6f
#define BLK     256
#define GRID_P  1064                 // persistent grid: 7 blocks/SM * 152 SMs

__device__ __forceinline__ float rcp_fast(float x) {
    float r; asm("rcp.approx.f32 %0, %1;" : "=f"(r) : "f"(x)); return r;
}
__device__ __forceinline__ float sqrt_fast(float x) {
    float r; asm("sqrt.approx.f32 %0, %1;" : "=f"(r) : "f"(x)); return r;
}

// loss for one box pair (algebraically reduced):
//   det_t = tww*thh/16, det_p = pww*phh/16     (rotation-invariant, no trig)
//   t1num = ths(dx^2+dy^2) - thd(c2t(dx^2-dy^2) + 2 s2t dx dy)
//   n2num = 2(ths*phs - thd*phd*cos(2rt-2rp))
//   dis   = (t1num+n2num)*16/(tww*thh) + log((tww*thh)/(pww*phh)) - 2
__device__ __forceinline__ float gd_loss_one(
    float px, float py, float pw, float ph, float prr,
    float tx, float ty, float tw, float th, float trr)
{
    pw = fminf(fmaxf(pw, 1e-7f), 1e7f);
    ph = fminf(fmaxf(ph, 1e-7f), 1e7f);
    tw = fminf(fmaxf(tw, 1e-7f), 1e7f);
    th = fminf(fmaxf(th, 1e-7f), 1e7f);

    const float pww = pw * pw, phh = ph * ph;
    const float tww = tw * tw, thh = th * th;

    const float phs = 0.125f * (pww + phh);
    const float phd = 0.125f * (pww - phh);
    const float ths = 0.125f * (tww + thh);
    const float thd = 0.125f * (tww - thh);

    float s2t, c2t;
    __sincosf(2.0f * trr, &s2t, &c2t);
    const float cdd = __cosf(2.0f * (trr - prr));   // cos(2rt - 2rp)

    const float dx = px - tx;
    const float dy = py - ty;
    const float dx2 = dx * dx, dy2 = dy * dy;
    const float sum2 = dx2 + dy2, dif2 = dx2 - dy2;
    const float dxy = dx * dy;

    const float rot   = fmaf(c2t, dif2, 2.0f * s2t * dxy);
    const float t1num = fmaf(ths, sum2, -thd * rot);
    const float n2num = 2.0f * fmaf(-thd * phd, cdd, ths * phs);

    const float dtt = tww * thh;                    // 16*det_t
    const float dpp = pww * phh;                    // 16*det_p
    const float invdt16 = 16.0f * rcp_fast(dtt);
    const float logterm = __logf(dtt * rcp_fast(dpp));

    const float dis = fmaf(t1num + n2num, invdt16, logterm - 2.0f);
    const float kl = fmaxf(dis, EPS_F);
    return 1.0f - rcp_fast(TAU_F + sqrt_fast(kl));
}

struct Pair10 {                       // 10 floats = one 2-box record
    float2 a, b, c, d, e;
};

__device__ __forceinline__ Pair10 load_pair(const float2* __restrict__ base) {
    Pair10 r;
    r.a = base[0]; r.b = base[1]; r.c = base[2]; r.d = base[3]; r.e = base[4];
    return r;
}

// compute both losses of a pair record:
//   box0 = (a.x a.y b.x b.y c.x), box1 = (c.y d.x d.y e.x e.y)
__device__ __forceinline__ float2 pair_loss(const Pair10& p, const Pair10& t) {
    float2 r;
    r.x = gd_loss_one(p.a.x, p.a.y, p.b.x, p.b.y, p.c.x,
                      t.a.x, t.a.y, t.b.x, t.b.y, t.c.x);
    r.y = gd_loss_one(p.c.y, p.d.x, p.d.y, p.e.x, p.e.y,
                      t.c.y, t.d.x, t.d.y, t.e.x, t.e.y);
    return r;
}

__global__ void __launch_bounds__(BLK, 4) gd_loss_kernel(
    const float* __restrict__ pred,
    const float* __restrict__ target,
    float* __restrict__ out,
    int n)
{
    const int npairs = n >> 1;                        // full 2-box pairs
    const int stride = gridDim.x * BLK;               // in pair units
    int i = blockIdx.x * BLK + threadIdx.x;

    // Handle odd trailing box (n odd) with the first thread.
    if ((n & 1) && (blockIdx.x == 0) && (threadIdx.x == 0)) {
        const float* p = pred   + (size_t)(n - 1) * 5;
        const float* t = target + (size_t)(n - 1) * 5;
        out[n - 1] = gd_loss_one(p[0], p[1], p[2], p[3], p[4],
                                 t[0], t[1], t[2], t[3], t[4]);
    }

    if (i >= npairs) return;

    const float2* __restrict__ p2base = (const float2*)pred;
    const float2* __restrict__ t2base = (const float2*)target;

    // Prime: load current pair's 10 float2.
    Pair10 pc = load_pair(p2base + (size_t)i * 5);
    Pair10 tc = load_pair(t2base + (size_t)i * 5);

    for (;;) {
        const int inext = i + stride;
        if (inext < npairs) {
            // Prefetch next iteration (10 independent LDG.64) BEFORE compute;
            // no dependency on pc/tc so these fly during the math below.
            Pair10 pn = load_pair(p2base + (size_t)inext * 5);
            Pair10 tn = load_pair(t2base + (size_t)inext * 5);

            float2 res = pair_loss(pc, tc);
            *(float2*)(out + (size_t)i * 2) = res;

            pc = pn; tc = tn; i = inext;
        } else {
            float2 res = pair_loss(pc, tc);
            *(float2*)(out + (size_t)i * 2) = res;
            break;
        }
    }
}

extern "C" void kernel_launch(void* const* d_in, const int* in_sizes, int n_in,
                              void* d_out, int out_size)
{
    const float* pred   = (const float*)d_in[0];
    const float* target = (const float*)d_in[1];
    // d_in[2] (weight) is unused by the reference computation (LOSS_WEIGHT=1).
    float* out = (float*)d_out;

    const int n = out_size;                      // N boxes; output [N,1] floats
    const int npairs = n >> 1;                   // 2M for N=4M
    int grid = GRID_P;
    const int maxGrid = (npairs + BLK - 1) / BLK;
    if (grid > maxGrid && maxGrid > 0) grid = maxGrid;
    if (grid < 1) grid = 1;
    gd_loss_kernel<<<grid, BLK>>>(pred, target, out, n);
}